// round 3
// baseline (speedup 1.0000x reference)
#include <cuda_runtime.h>

#define Hc   128
#define Wc   128
#define Cc   64
#define Bc   8
#define COUTc 64

__device__ float g_xh[Bc * Hc * Wc * Cc];      // [b][y][x][c]
__device__ float g_wt[9 * Cc * COUTc];         // [k][c][o]

// Dummy launch to rotate dcn_main into ncu's -s 5 -c 1 capture slot.
__global__ void dummy_kernel() {}

// ---------------------------------------------------------------------------
// NCHW -> NHWC transpose of x.
// ---------------------------------------------------------------------------
__global__ void transpose_x_kernel(const float* __restrict__ x) {
    __shared__ float t[64][33];
    int blk = blockIdx.x;
    int wt  = blk & 3;
    int h   = (blk >> 2) & 127;
    int b   = blk >> 9;
    int w0  = wt << 5;

    #pragma unroll
    for (int i = 0; i < 8; i++) {
        int idx = i * 256 + threadIdx.x;
        int c = idx >> 5;
        int w = idx & 31;
        t[c][w] = x[(((b * 64 + c) * 128 + h) << 7) + w0 + w];
    }
    __syncthreads();
    #pragma unroll
    for (int i = 0; i < 8; i++) {
        int idx = i * 256 + threadIdx.x;
        int c = idx & 63;
        int w = idx >> 6;
        g_xh[((((b * 128 + h) << 7) + w0 + w) << 6) + c] = t[c][w];
    }
}

// weight [o][c][k] -> [k][c][o]
__global__ void transpose_w_kernel(const float* __restrict__ wsrc) {
    int idx = blockIdx.x * 256 + threadIdx.x;
    if (idx < 9 * Cc * COUTc) {
        int o = idx & 63;
        int c = (idx >> 6) & 63;
        int k = idx >> 12;
        g_wt[idx] = wsrc[(o * 64 + c) * 9 + k];
    }
}

#define FMA2(acc, a, b) \
    asm("fma.rn.f32x2 %0, %1, %2, %0;" : "+l"(acc) : "l"(a), "l"(b))

__device__ __forceinline__ unsigned long long dup2(float v) {
    unsigned long long r;
    asm("mov.b64 %0, {%1, %1};" : "=l"(r) : "f"(v));
    return r;
}

// ---------------------------------------------------------------------------
// Main fused DCNv2, warp-specialized:
//   warps 0-7  : consumers — pure smem GEMM (no global/staging instructions)
//   warps 8-9  : producers — bilinear gather + weight/coord staging, one tap
//                ahead of the consumers (double-buffered cols/w/coords).
// Grid: B*Ho = 1024 CTAs (one output row), 320 threads, 2 CTAs/SM.
// acc layout: acc[o-pair][px] so weight PAIRS load as 64-bit smem broadcasts
// (no duplication); per-px scalar dup is one mov.b64 on the alu pipe.
// smem: cols[2][64][128] 64KB | w[2][64][64] 32KB | coords[2][1K] 8KB = 104KB
// ---------------------------------------------------------------------------
__global__ __launch_bounds__(320, 2)
void dcn_main_kernel(const float* __restrict__ offset,
                     const float* __restrict__ mask,
                     const float* __restrict__ bias,
                     float* __restrict__ out)
{
    extern __shared__ float smem[];
    float* colsbuf = smem;                    // 2 x 8192 floats
    float* wbuf    = smem + 16384;            // 2 x 4096 floats
    float* cbase   = smem + 16384 + 8192;     // 2 x 1024 floats

    const int tid  = threadIdx.x;
    const int lane = tid & 31;
    const int warp = tid >> 5;
    const int ho   = blockIdx.x & 127;
    const int b    = blockIdx.x >> 7;
    const bool producer = (warp >= 8);
    const int ptid = tid - 256;               // 0..63 for producers

    const float* xb = g_xh + (size_t)b * (Hc * Wc * Cc);

    // ---- producers: coords for tap kk (2 px per producer thread) ----
    auto coords = [&](int kk) {
        float* swgt = cbase + ((kk & 1) << 10);
        int*   soff = (int*)(swgt + 512);
        int kr = kk / 3, kc = kk - kr * 3;
        #pragma unroll
        for (int h = 0; h < 2; h++) {
            int wo = ptid + (h << 6);
            float dx = offset[(((size_t)b * 18 + 2 * kk    ) * 128 + ho) * 128 + wo];
            float dy = offset[(((size_t)b * 18 + 2 * kk + 1) * 128 + ho) * 128 + wo];
            float m  = mask  [(((size_t)b * 9  + kk        ) * 128 + ho) * 128 + wo];
            float py = (float)(ho - 1 + kr) + dy;
            float px = (float)(wo - 1 + kc) + dx;
            float y0f = floorf(py), x0f = floorf(px);
            float fy = py - y0f, fx = px - x0f;
            float gy = 1.0f - fy, gx = 1.0f - fx;
            float y1f = y0f + 1.0f, x1f = x0f + 1.0f;
            bool vy0 = (y0f >= 0.0f) && (y0f <= 127.0f);
            bool vy1 = (y1f >= 0.0f) && (y1f <= 127.0f);
            bool vx0 = (x0f >= 0.0f) && (x0f <= 127.0f);
            bool vx1 = (x1f >= 0.0f) && (x1f <= 127.0f);
            int iy0 = min(max((int)y0f, 0), 127);
            int iy1 = min(max((int)y1f, 0), 127);
            int ix0 = min(max((int)x0f, 0), 127);
            int ix1 = min(max((int)x1f, 0), 127);
            swgt[wo]       = (vy0 && vx0) ? gy * gx * m : 0.0f;
            swgt[128 + wo] = (vy0 && vx1) ? gy * fx * m : 0.0f;
            swgt[256 + wo] = (vy1 && vx0) ? fy * gx * m : 0.0f;
            swgt[384 + wo] = (vy1 && vx1) ? fy * fx * m : 0.0f;
            soff[wo]       = (iy0 * 128 + ix0) << 6;
            soff[128 + wo] = (iy0 * 128 + ix1) << 6;
            soff[256 + wo] = (iy1 * 128 + ix0) << 6;
            soff[384 + wo] = (iy1 * 128 + ix1) << 6;
        }
    };

    // ---- producers: stage plain weights w[c][o] for tap kk ----
    auto stage_w = [&](int kk) {
        const float4* src = (const float4*)(g_wt + kk * 4096);
        float4*       dst = (float4*)(wbuf + ((kk & 1) << 12));
        #pragma unroll
        for (int i = 0; i < 16; i++)
            dst[i * 64 + ptid] = src[i * 64 + ptid];
    };

    // ---- producers: bilinear-gather cols[c][px] for tap kk ----
    auto stage_cols = [&](int kk) {
        float* cols = colsbuf + ((kk & 1) << 13);
        float* swgt = cbase + ((kk & 1) << 10);
        int*   soff = (int*)(swgt + 512);
        #pragma unroll 8
        for (int i = 0; i < 32; i++) {
            int sub = i * 64 + ptid;
            int cq  = sub & 15;        // channel quad
            int px  = sub >> 4;        // pixel
            int cb  = cq << 2;

            float w00 = swgt[px],       w01 = swgt[128 + px];
            float w10 = swgt[256 + px], w11 = swgt[384 + px];

            float4 c00 = *(const float4*)(xb + soff[px]       + cb);
            float4 c01 = *(const float4*)(xb + soff[128 + px] + cb);
            float4 c10 = *(const float4*)(xb + soff[256 + px] + cb);
            float4 c11 = *(const float4*)(xb + soff[384 + px] + cb);

            float vx = c00.x * w00 + c01.x * w01 + c10.x * w10 + c11.x * w11;
            float vy = c00.y * w00 + c01.y * w01 + c10.y * w10 + c11.y * w11;
            float vz = c00.z * w00 + c01.z * w01 + c10.z * w10 + c11.z * w11;
            float vw = c00.w * w00 + c01.w * w01 + c10.w * w10 + c11.w * w11;

            int sg    = (px >> 2) ^ (cq & 7);     // swizzled px-group
            int wbase = (cb << 7) + (sg << 2) + (px & 3);
            cols[wbase]       = vx;
            cols[wbase + 128] = vy;
            cols[wbase + 256] = vz;
            cols[wbase + 384] = vw;
        }
    };

    // acc[o-pair j][px p]: f32x2 = outputs (o0+2j, o0+2j+1) at pixel lane*4+p
    unsigned long long acc[4][4];
    #pragma unroll
    for (int j = 0; j < 4; j++)
        #pragma unroll
        for (int p = 0; p < 4; p++) acc[j][p] = 0ull;

    // ---- prologue ----
    if (producer) { coords(0); coords(1); }
    __syncthreads();
    if (producer) { stage_w(0); stage_cols(0); }

    #pragma unroll 1
    for (int k = 0; k < 9; k++) {
        __syncthreads();   // staging(k) visible; GEMM(k-1) done with its buffers

        if (producer) {
            if (k < 8) { stage_w(k + 1); stage_cols(k + 1); }
            if (k < 7) coords(k + 2);
        } else {
            const float* cols = colsbuf + ((k & 1) << 13);
            const float* wk   = wbuf + ((k & 1) << 12);
            const int o0 = warp << 3;
            #pragma unroll 4
            for (int c = 0; c < 64; c++) {
                ulonglong2 wA = *(const ulonglong2*)(wk + (c << 6) + o0);     // (w0,w1),(w2,w3)
                ulonglong2 wB = *(const ulonglong2*)(wk + (c << 6) + o0 + 4); // (w4,w5),(w6,w7)
                int col = (lane ^ ((c >> 2) & 7)) << 2;
                float4 cv = *(const float4*)(cols + (c << 7) + col);
                unsigned long long d0 = dup2(cv.x), d1 = dup2(cv.y);
                unsigned long long d2 = dup2(cv.z), d3 = dup2(cv.w);
                FMA2(acc[0][0], wA.x, d0); FMA2(acc[0][1], wA.x, d1);
                FMA2(acc[0][2], wA.x, d2); FMA2(acc[0][3], wA.x, d3);
                FMA2(acc[1][0], wA.y, d0); FMA2(acc[1][1], wA.y, d1);
                FMA2(acc[1][2], wA.y, d2); FMA2(acc[1][3], wA.y, d3);
                FMA2(acc[2][0], wB.x, d0); FMA2(acc[2][1], wB.x, d1);
                FMA2(acc[2][2], wB.x, d2); FMA2(acc[2][3], wB.x, d3);
                FMA2(acc[3][0], wB.y, d0); FMA2(acc[3][1], wB.y, d1);
                FMA2(acc[3][2], wB.y, d2); FMA2(acc[3][3], wB.y, d3);
            }
        }
    }

    // ---- epilogue (consumers): bias + NCHW fp32 store ----
    if (!producer) {
        const int o0  = warp << 3;
        const int px0 = lane << 2;
        union U { unsigned long long u; float2 f; };
        #pragma unroll
        for (int j = 0; j < 4; j++) {
            U a0, a1, a2, a3;
            a0.u = acc[j][0]; a1.u = acc[j][1]; a2.u = acc[j][2]; a3.u = acc[j][3];
            int oe = o0 + 2 * j;
            float be = bias[oe], bo = bias[oe + 1];
            float4 re = make_float4(a0.f.x + be, a1.f.x + be, a2.f.x + be, a3.f.x + be);
            float4 ro = make_float4(a0.f.y + bo, a1.f.y + bo, a2.f.y + bo, a3.f.y + bo);
            *(float4*)(out + ((((size_t)b * COUTc + oe    ) * Hc + ho) * Wc + px0)) = re;
            *(float4*)(out + ((((size_t)b * COUTc + oe + 1) * Hc + ho) * Wc + px0)) = ro;
        }
    }
}

// ---------------------------------------------------------------------------
extern "C" void kernel_launch(void* const* d_in, const int* in_sizes, int n_in,
                              void* d_out, int out_size) {
    const float* x      = (const float*)d_in[0];
    const float* offset = (const float*)d_in[1];
    const float* mask   = (const float*)d_in[2];
    const float* weight = (const float*)d_in[3];
    const float* bias   = (const float*)d_in[4];
    float* out = (float*)d_out;

    cudaFuncSetAttribute(dcn_main_kernel,
                         cudaFuncAttributeMaxDynamicSharedMemorySize, 106496);

    dummy_kernel<<<1, 32>>>();
    transpose_x_kernel<<<4096, 256>>>(x);
    transpose_w_kernel<<<144, 256>>>(weight);
    dcn_main_kernel<<<1024, 320, 106496>>>(offset, mask, bias, out);
}

// round 8
// speedup vs baseline: 2.7097x; 2.7097x over previous
#include <cuda_runtime.h>
#include <cuda_fp16.h>
#include <cstdint>

#define Hc   128
#define Wc   128
#define Cc   64
#define Bc   8
#define COUTc 64

__device__ float  g_xh[Bc * Hc * Wc * Cc];   // x in NHWC: [b][y][x][c]
__device__ __half g_wh[9 * 4096];            // per-tap B tile [o][c] fp16, SW128-swizzled

// Keep 4-launch structure so ncu -s 5 -c 1 lands on dcn_main_kernel.
__global__ void dummy_kernel() {}

// ---------------------------------------------------------------------------
// NCHW -> NHWC transpose of x.
// ---------------------------------------------------------------------------
__global__ void transpose_x_kernel(const float* __restrict__ x) {
    __shared__ float t[64][33];
    int blk = blockIdx.x;
    int wt  = blk & 3;
    int h   = (blk >> 2) & 127;
    int b   = blk >> 9;
    int w0  = wt << 5;

    #pragma unroll
    for (int i = 0; i < 8; i++) {
        int idx = i * 256 + threadIdx.x;
        int c = idx >> 5;
        int w = idx & 31;
        t[c][w] = x[(((b * 64 + c) * 128 + h) << 7) + w0 + w];
    }
    __syncthreads();
    #pragma unroll
    for (int i = 0; i < 8; i++) {
        int idx = i * 256 + threadIdx.x;
        int c = idx & 63;
        int w = idx >> 6;
        g_xh[((((b * 128 + h) << 7) + w0 + w) << 6) + c] = t[c][w];
    }
}

// ---------------------------------------------------------------------------
// Weight prep: [o][c][kh][kw] fp32 -> per-tap [o rows][c cols] fp16,
// 128B rows, SW128-swizzled, ready for ldmatrix.
// ---------------------------------------------------------------------------
__global__ void prep_w_kernel(const float* __restrict__ wsrc) {
    int idx = blockIdx.x * 256 + threadIdx.x;
    if (idx < 9 * 4096) {
        int k = idx >> 12;
        int r = idx & 4095;
        int o = r >> 6;
        int c = r & 63;
        float v = wsrc[(o * 64 + c) * 9 + k];
        int byte = (o << 7) + (c << 1);
        int sw   = byte ^ ((byte >> 3) & 0x70);
        g_wh[(k << 12) + (sw >> 1)] = __float2half(v);
    }
}

// ---------------------------------------------------------------------------
// helpers
// ---------------------------------------------------------------------------
__device__ __forceinline__ int sw128(int b) { return b ^ ((b >> 3) & 0x70); }

__device__ __forceinline__ uint32_t smem_u32(const void* p) {
    uint32_t a;
    asm("{ .reg .u64 t; cvta.to.shared.u64 t, %1; cvt.u32.u64 %0, t; }"
        : "=r"(a) : "l"(p));
    return a;
}
__device__ __forceinline__ void ldsm_x4(uint32_t* r, uint32_t a) {
    asm volatile("ldmatrix.sync.aligned.m8n8.x4.shared.b16 {%0,%1,%2,%3}, [%4];"
                 : "=r"(r[0]), "=r"(r[1]), "=r"(r[2]), "=r"(r[3]) : "r"(a));
}
__device__ __forceinline__ void ldsm_x2(uint32_t* r, uint32_t a) {
    asm volatile("ldmatrix.sync.aligned.m8n8.x2.shared.b16 {%0,%1}, [%2];"
                 : "=r"(r[0]), "=r"(r[1]) : "r"(a));
}
#define MMA16816(c, a, bb)                                                    \
    asm volatile("mma.sync.aligned.m16n8k16.row.col.f32.f16.f16.f32 "         \
                 "{%0,%1,%2,%3}, {%4,%5,%6,%7}, {%8,%9}, {%0,%1,%2,%3};"      \
                 : "+f"((c)[0]), "+f"((c)[1]), "+f"((c)[2]), "+f"((c)[3])     \
                 : "r"((a)[0]), "r"((a)[1]), "r"((a)[2]), "r"((a)[3]),        \
                   "r"((bb)[0]), "r"((bb)[1]))

// smem byte layout
#define OFF_A 0        // 2 x 16384 : A tiles [128px][64c] fp16, SW128
#define OFF_B 32768    // 2 x 8192  : B tiles [64o][64c] fp16, SW128
#define OFF_C 49152    // 2 x 4096  : coords (512 f32 wgt + 512 i32 off)
#define SMEM_BYTES 57344

// ---------------------------------------------------------------------------
// Main fused DCNv2 with mma.sync fp16 tensor cores.
// Grid: B*Ho = 1024 CTAs (one output row of 128 px), 256 threads, 2 CTAs/SM.
// Per tap: all threads bilinear-gather A_k into fp16 SW128 smem + copy B_k +
// coords(k+1); one __syncthreads; 8 warps do M32xN32 HMMA tiles (K=64).
// Epilogue transposes D through smem (pitch 132) for coalesced NCHW stores.
// ---------------------------------------------------------------------------
__global__ __launch_bounds__(256, 2)
void dcn_main_kernel(const float* __restrict__ offset,
                     const float* __restrict__ mask,
                     const float* __restrict__ bias,
                     float* __restrict__ out)
{
    extern __shared__ float smem[];
    char* smc = (char*)smem;

    const int tid  = threadIdx.x;
    const int lane = tid & 31;
    const int warp = tid >> 5;
    const int ho   = blockIdx.x & 127;
    const int b    = blockIdx.x >> 7;

    const float*   xb   = g_xh + (size_t)b * (Hc * Wc * Cc);
    const uint32_t sb32 = smem_u32(smem);

    // ---- coords for tap kk into buffer (kk&1) ----
    auto coords = [&](int kk) {
        if (tid < 128) {
            float* swgt = (float*)(smc + OFF_C + ((kk & 1) << 12));
            int*   soff = (int*)(swgt + 512);
            int wo = tid;
            int kr = kk / 3, kc = kk - kr * 3;
            float dx = offset[(((size_t)b * 18 + 2 * kk    ) * 128 + ho) * 128 + wo];
            float dy = offset[(((size_t)b * 18 + 2 * kk + 1) * 128 + ho) * 128 + wo];
            float m  = mask  [(((size_t)b * 9  + kk        ) * 128 + ho) * 128 + wo];
            float py = (float)(ho - 1 + kr) + dy;
            float px = (float)(wo - 1 + kc) + dx;
            float y0f = floorf(py), x0f = floorf(px);
            float fy = py - y0f, fx = px - x0f;
            float gy = 1.0f - fy, gx = 1.0f - fx;
            float y1f = y0f + 1.0f, x1f = x0f + 1.0f;
            bool vy0 = (y0f >= 0.0f) && (y0f <= 127.0f);
            bool vy1 = (y1f >= 0.0f) && (y1f <= 127.0f);
            bool vx0 = (x0f >= 0.0f) && (x0f <= 127.0f);
            bool vx1 = (x1f >= 0.0f) && (x1f <= 127.0f);
            int iy0 = min(max((int)y0f, 0), 127);
            int iy1 = min(max((int)y1f, 0), 127);
            int ix0 = min(max((int)x0f, 0), 127);
            int ix1 = min(max((int)x1f, 0), 127);
            swgt[wo]       = (vy0 && vx0) ? gy * gx * m : 0.0f;
            swgt[128 + wo] = (vy0 && vx1) ? gy * fx * m : 0.0f;
            swgt[256 + wo] = (vy1 && vx0) ? fy * gx * m : 0.0f;
            swgt[384 + wo] = (vy1 && vx1) ? fy * fx * m : 0.0f;
            soff[wo]       = (iy0 * 128 + ix0) << 6;
            soff[128 + wo] = (iy0 * 128 + ix1) << 6;
            soff[256 + wo] = (iy1 * 128 + ix0) << 6;
            soff[384 + wo] = (iy1 * 128 + ix1) << 6;
        }
    };

    // ---- bilinear-gather A_k[px][c] -> fp16 SW128 smem tile ----
    auto stageA = [&](int kk) {
        char*  A    = smc + OFF_A + ((kk & 1) << 14);
        float* swgt = (float*)(smc + OFF_C + ((kk & 1) << 12));
        int*   soff = (int*)(swgt + 512);
        #pragma unroll
        for (int i = 0; i < 8; i++) {
            int sub = i * 256 + tid;
            int cq  = sub & 15;       // channel quad (c = cq*4)
            int px  = sub >> 4;       // pixel 0..127
            int cb  = cq << 2;

            float w00 = swgt[px],       w01 = swgt[128 + px];
            float w10 = swgt[256 + px], w11 = swgt[384 + px];

            float4 c00 = *(const float4*)(xb + soff[px]       + cb);
            float4 c01 = *(const float4*)(xb + soff[128 + px] + cb);
            float4 c10 = *(const float4*)(xb + soff[256 + px] + cb);
            float4 c11 = *(const float4*)(xb + soff[384 + px] + cb);

            float vx = c00.x * w00 + c01.x * w01 + c10.x * w10 + c11.x * w11;
            float vy = c00.y * w00 + c01.y * w01 + c10.y * w10 + c11.y * w11;
            float vz = c00.z * w00 + c01.z * w01 + c10.z * w10 + c11.z * w11;
            float vw = c00.w * w00 + c01.w * w01 + c10.w * w10 + c11.w * w11;

            union { __half2 h[2]; uint2 u; } pk;
            pk.h[0] = __floats2half2_rn(vx, vy);
            pk.h[1] = __floats2half2_rn(vz, vw);

            int byte = (px << 7) + (cq << 3);        // 8B-aligned
            *(uint2*)(A + sw128(byte)) = pk.u;
        }
    };

    // ---- copy pre-swizzled B tile (8KB) ----
    auto copyB = [&](int kk) {
        const uint4* src = (const uint4*)(g_wh + (kk << 12));
        uint4*       dst = (uint4*)(smc + OFF_B + ((kk & 1) << 13));
        dst[tid]       = src[tid];
        dst[256 + tid] = src[256 + tid];
    };

    // accumulators: [mi][nj][4]  (warp tile M32 x N32)
    float acc[2][4][4];
    #pragma unroll
    for (int mi = 0; mi < 2; mi++)
        #pragma unroll
        for (int nj = 0; nj < 4; nj++)
            #pragma unroll
            for (int r = 0; r < 4; r++) acc[mi][nj][r] = 0.0f;

    const int mtile = (warp & 3) << 5;   // px base
    const int ntile = (warp >> 2) << 5;  // o base

    coords(0);
    __syncthreads();

    #pragma unroll 1
    for (int k = 0; k < 9; k++) {
        stageA(k);
        copyB(k);
        if (k < 8) coords(k + 1);
        __syncthreads();

        const uint32_t Ab = sb32 + OFF_A + ((k & 1) << 14);
        const uint32_t Bb = sb32 + OFF_B + ((k & 1) << 13);
        #pragma unroll
        for (int kc = 0; kc < 4; kc++) {
            uint32_t a0[4], a1[4];
            {
                int rl = (lane & 7) + ((lane >> 3) & 1) * 8;
                int cb = kc * 32 + (lane >> 4) * 16;
                ldsm_x4(a0, Ab + sw128(((mtile + rl) << 7) + cb));
                ldsm_x4(a1, Ab + sw128(((mtile + 16 + rl) << 7) + cb));
            }
            #pragma unroll
            for (int nj = 0; nj < 4; nj++) {
                int rl = ntile + nj * 8 + (lane & 7);
                int cb = kc * 32 + ((lane >> 3) & 1) * 16;
                uint32_t bb[2];
                ldsm_x2(bb, Bb + sw128((rl << 7) + cb));
                MMA16816(acc[0][nj], a0, bb);
                MMA16816(acc[1][nj], a1, bb);
            }
        }
    }

    // ---- epilogue: transpose D through smem (pitch 132), coalesced stores ----
    __syncthreads();
    float* T = smem;                       // 64 x 132 f32 = 33.8KB (reuses A+B)
    {
        int g  = lane >> 2;
        int i2 = (lane & 3) << 1;
        #pragma unroll
        for (int mi = 0; mi < 2; mi++)
            #pragma unroll
            for (int nj = 0; nj < 4; nj++) {
                int px = mtile + mi * 16 + g;
                int o  = ntile + nj * 8 + i2;
                T[o * 132 + px]           = acc[mi][nj][0];
                T[(o + 1) * 132 + px]     = acc[mi][nj][1];
                T[o * 132 + px + 8]       = acc[mi][nj][2];
                T[(o + 1) * 132 + px + 8] = acc[mi][nj][3];
            }
    }
    __syncthreads();
    #pragma unroll
    for (int i = 0; i < 8; i++) {
        int idx = i * 256 + tid;           // 2048 float4
        int o   = idx >> 5;
        int p4  = (idx & 31) << 2;
        float4 v = *(float4*)(T + o * 132 + p4);
        float bv = bias[o];
        v.x += bv; v.y += bv; v.z += bv; v.w += bv;
        *(float4*)(out + (((size_t)b * 64 + o) * 128 + ho) * 128 + p4) = v;
    }
}

// ---------------------------------------------------------------------------
extern "C" void kernel_launch(void* const* d_in, const int* in_sizes, int n_in,
                              void* d_out, int out_size) {
    const float* x      = (const float*)d_in[0];
    const float* offset = (const float*)d_in[1];
    const float* mask   = (const float*)d_in[2];
    const float* weight = (const float*)d_in[3];
    const float* bias   = (const float*)d_in[4];
    float* out = (float*)d_out;

    cudaFuncSetAttribute(dcn_main_kernel,
                         cudaFuncAttributeMaxDynamicSharedMemorySize, SMEM_BYTES);

    dummy_kernel<<<1, 32>>>();
    transpose_x_kernel<<<4096, 256>>>(x);
    prep_w_kernel<<<144, 256>>>(weight);
    dcn_main_kernel<<<1024, 256, SMEM_BYTES>>>(offset, mask, bias, out);
}